// round 1
// baseline (speedup 1.0000x reference)
#include <cuda_runtime.h>

#define Nn 32768
#define Dd 256
#define Kk 8192

// Scratch (no allocations allowed in kernel_launch)
__device__ float g_wn[Kk];    // 0.5 * ||w_k||^2
__device__ int   g_idx[Nn];   // argmin index per row

// ---------------------------------------------------------------------------
// Kernel 1: wn[k] = 0.5 * sum_d W[k][d]^2   (one warp per codeword)
// ---------------------------------------------------------------------------
__global__ void wnorm_kernel(const float* __restrict__ W) {
    int k = blockIdx.x * 8 + (threadIdx.x >> 5);
    int lane = threadIdx.x & 31;
    const float4* wp = (const float4*)(W + (size_t)k * Dd);
    float4 a = wp[lane * 2];
    float4 b = wp[lane * 2 + 1];
    float s = a.x * a.x + a.y * a.y + a.z * a.z + a.w * a.w
            + b.x * b.x + b.y * b.y + b.z * b.z + b.w * b.w;
    #pragma unroll
    for (int o = 16; o > 0; o >>= 1) s += __shfl_xor_sync(0xffffffffu, s, o);
    if (lane == 0) g_wn[k] = 0.5f * s;
}

// ---------------------------------------------------------------------------
// Kernel 2: fused GEMM + argmax.
// score[n][k] = x_n . w_k - 0.5*||w_k||^2 ; argmax over k == argmin distance.
// Tile: BM=128 rows x BKC=128 cols, d-chunk BD=16, 256 threads, 8x8 per thread.
// ---------------------------------------------------------------------------
#define BM  128
#define BKC 128
#define BD  16
#define TM  8
#define TN  8

__global__ __launch_bounds__(256, 2)
void gemm_argmax_kernel(const float* __restrict__ X, const float* __restrict__ W) {
    __shared__ float Xs[BD][BM + 4];
    __shared__ float Ws[BD][BKC + 4];
    __shared__ float wns[BKC];
    __shared__ float redv[16][17];
    __shared__ int   redi[16][17];

    const int tid = threadIdx.x;
    const int tx  = tid & 15;   // col group
    const int ty  = tid >> 4;   // row group
    const int row0 = blockIdx.x * BM;

    float best[TM];
    int   bidx[TM];
    #pragma unroll
    for (int i = 0; i < TM; i++) { best[i] = -3.4e38f; bidx[i] = 0; }

    for (int kc = 0; kc < Kk; kc += BKC) {
        float acc[TM][TN];
        #pragma unroll
        for (int i = 0; i < TM; i++)
            #pragma unroll
            for (int j = 0; j < TN; j++) acc[i][j] = 0.0f;

        if (tid < BKC) wns[tid] = g_wn[kc + tid];

        for (int dc = 0; dc < Dd; dc += BD) {
            // Load 128x16 X tile and 128x16 W tile (transposed into smem)
            #pragma unroll
            for (int q = 0; q < 2; q++) {
                int f = tid * 2 + q;        // 0..511
                int r = f >> 2;             // 0..127
                int c = (f & 3) << 2;       // 0,4,8,12
                float4 xv = *(const float4*)(X + (size_t)(row0 + r) * Dd + dc + c);
                Xs[c + 0][r] = xv.x; Xs[c + 1][r] = xv.y;
                Xs[c + 2][r] = xv.z; Xs[c + 3][r] = xv.w;
                float4 wv = *(const float4*)(W + (size_t)(kc + r) * Dd + dc + c);
                Ws[c + 0][r] = wv.x; Ws[c + 1][r] = wv.y;
                Ws[c + 2][r] = wv.z; Ws[c + 3][r] = wv.w;
            }
            __syncthreads();
            #pragma unroll
            for (int d = 0; d < BD; d++) {
                float a[TM], b[TN];
                *(float4*)&a[0] = *(const float4*)&Xs[d][ty * TM];
                *(float4*)&a[4] = *(const float4*)&Xs[d][ty * TM + 4];
                *(float4*)&b[0] = *(const float4*)&Ws[d][tx * TN];
                *(float4*)&b[4] = *(const float4*)&Ws[d][tx * TN + 4];
                #pragma unroll
                for (int i = 0; i < TM; i++)
                    #pragma unroll
                    for (int j = 0; j < TN; j++)
                        acc[i][j] += a[i] * b[j];
            }
            __syncthreads();
        }

        // Fused argmax epilogue for this 128-col chunk.
        // Strict '>' keeps the earliest (lowest) k on ties, matching argmin.
        #pragma unroll
        for (int i = 0; i < TM; i++) {
            #pragma unroll
            for (int j = 0; j < TN; j++) {
                float s = acc[i][j] - wns[tx * TN + j];
                if (s > best[i]) { best[i] = s; bidx[i] = kc + tx * TN + j; }
            }
        }
        __syncthreads();  // protect wns before next chunk's load
    }

    // Cross-thread reduction: 16 tx-threads cover each row.
    #pragma unroll
    for (int i = 0; i < TM; i++) {
        redv[ty][tx] = best[i];
        redi[ty][tx] = bidx[i];
        __syncthreads();
        if (tx == 0) {
            float bv = redv[ty][0];
            int   bi = redi[ty][0];
            #pragma unroll
            for (int t = 1; t < 16; t++) {
                float v  = redv[ty][t];
                int   ii = redi[ty][t];
                if (v > bv || (v == bv && ii < bi)) { bv = v; bi = ii; }
            }
            g_idx[row0 + ty * TM + i] = bi;
        }
        __syncthreads();
    }
}

// ---------------------------------------------------------------------------
// Kernel 3: gather codebook rows + write indices
// ---------------------------------------------------------------------------
__global__ void gather_kernel(const float* __restrict__ W,
                              float* __restrict__ outq,
                              float* __restrict__ outi,
                              int write_idx) {
    int n = blockIdx.x;
    int idx = g_idx[n];
    const float4* src = (const float4*)(W + (size_t)idx * Dd);
    float4* dst = (float4*)(outq + (size_t)n * Dd);
    dst[threadIdx.x] = src[threadIdx.x];   // 64 threads * float4 = 256 floats
    if (threadIdx.x == 0 && write_idx) outi[n] = (float)idx;
}

// ---------------------------------------------------------------------------
extern "C" void kernel_launch(void* const* d_in, const int* in_sizes, int n_in,
                              void* d_out, int out_size) {
    const float* X = (const float*)d_in[0];   // inputs [N, D]
    const float* W = (const float*)d_in[1];   // weight [K, D]
    float* out = (float*)d_out;

    wnorm_kernel<<<Kk / 8, 256>>>(W);
    gemm_argmax_kernel<<<Nn / BM, 256>>>(X, W);

    int write_idx = (out_size >= Nn * Dd + Nn) ? 1 : 0;
    gather_kernel<<<Nn, 64>>>(W, out, out + (size_t)Nn * Dd, write_idx);
}

// round 3
// speedup vs baseline: 1.7771x; 1.7771x over previous
#include <cuda_runtime.h>
#include <cuda_fp16.h>
#include <cstdint>

#define Nn 32768
#define Dd 256
#define Kk 8192

#define BM 128
#define BN 128
#define NCHUNK (Kk / BN)       // 64
#define NK 24                  // k-iterations per chunk: 768 / 32
#define CAP 1024u
#define MARGIN 0.01f

// ---------------------------------------------------------------------------
// Device scratch (no allocations allowed)
// ---------------------------------------------------------------------------
__device__ __half g_xh[Nn * Dd];
__device__ __half g_xl[Nn * Dd];
__device__ __half g_wh[Kk * Dd];
__device__ __half g_wl[Kk * Dd];
__device__ float g_wn[Kk];
__device__ int g_idx[Nn];
__device__ unsigned int g_flag[CAP];
__device__ unsigned int g_nflag;
__device__ unsigned long long g_res[Nn];

// ---------------------------------------------------------------------------
__device__ __forceinline__ uint32_t smem_to_u32(const void* p) {
    uint32_t a;
    asm("{ .reg .u64 t; cvta.to.shared.u64 t, %1; cvt.u32.u64 %0, t; }"
        : "=r"(a) : "l"(p));
    return a;
}

__device__ __forceinline__ void cpasync16(uint32_t dst, const void* src) {
    asm volatile("cp.async.ca.shared.global [%0], [%1], 16;" :: "r"(dst), "l"(src));
}

#define CP_COMMIT() asm volatile("cp.async.commit_group;" ::: "memory")
#define CP_WAIT1()  asm volatile("cp.async.wait_group 1;" ::: "memory")
#define CP_WAIT0()  asm volatile("cp.async.wait_group 0;" ::: "memory")

#define LDSM_X4(r0, r1, r2, r3, addr) \
    asm volatile("ldmatrix.sync.aligned.m8n8.x4.shared.b16 {%0,%1,%2,%3}, [%4];" \
        : "=r"(r0), "=r"(r1), "=r"(r2), "=r"(r3) : "r"(addr))

#define MMA16816(c, a, b) \
    asm volatile("mma.sync.aligned.m16n8k16.row.col.f32.f16.f16.f32 " \
        "{%0,%1,%2,%3}, {%4,%5,%6,%7}, {%8,%9}, {%0,%1,%2,%3};" \
        : "+f"((c)[0]), "+f"((c)[1]), "+f"((c)[2]), "+f"((c)[3]) \
        : "r"((a)[0]), "r"((a)[1]), "r"((a)[2]), "r"((a)[3]), \
          "r"((b)[0]), "r"((b)[1]))

// SMEM layout (dynamic):
//  A tiles: [0, 20480)    = 2 bufs x 128 rows x 80B
//  B tiles: [20480, 40960)
//  wns:     [40960, 41472) 128 floats
//  merge:   mv1 [41472, 45568), mv2 [45568, 49664), mi [49664, 53760)
#define SM_A   0
#define SM_B   20480
#define SM_WNS 40960
#define SM_MV1 41472
#define SM_MV2 45568
#define SM_MI  49664
#define SMEM_TOTAL 53760
#define TBUF 10240   // one tile buffer: 128 * 80

// ---------------------------------------------------------------------------
// Preprocessing: fp16 hi/lo split
// ---------------------------------------------------------------------------
__global__ void convx_kernel(const float* __restrict__ X) {
    int i = blockIdx.x * 256 + threadIdx.x;
    if (i == 0) g_nflag = 0;
    if (i < Nn * Dd / 2) {
        float2 v = ((const float2*)X)[i];
        __half hx = __float2half(v.x);
        __half hy = __float2half(v.y);
        __half lx = __float2half(v.x - __half2float(hx));
        __half ly = __float2half(v.y - __half2float(hy));
        ((__half2*)g_xh)[i] = __halves2half2(hx, hy);
        ((__half2*)g_xl)[i] = __halves2half2(lx, ly);
    }
}

__global__ void convw_kernel(const float* __restrict__ W) {
    int i = blockIdx.x * 256 + threadIdx.x;
    if (i < Kk * Dd / 2) {
        float2 v = ((const float2*)W)[i];
        __half hx = __float2half(v.x);
        __half hy = __float2half(v.y);
        __half lx = __float2half(v.x - __half2float(hx));
        __half ly = __float2half(v.y - __half2float(hy));
        ((__half2*)g_wh)[i] = __halves2half2(hx, hy);
        ((__half2*)g_wl)[i] = __halves2half2(lx, ly);
    }
}

__global__ void wnorm_kernel(const float* __restrict__ W) {
    int k = blockIdx.x * 8 + (threadIdx.x >> 5);
    int lane = threadIdx.x & 31;
    const float4* wp = (const float4*)(W + (size_t)k * Dd);
    float4 a = wp[lane * 2];
    float4 b = wp[lane * 2 + 1];
    float s = a.x * a.x + a.y * a.y + a.z * a.z + a.w * a.w
            + b.x * b.x + b.y * b.y + b.z * b.z + b.w * b.w;
    #pragma unroll
    for (int o = 16; o > 0; o >>= 1) s += __shfl_xor_sync(0xffffffffu, s, o);
    if (lane == 0) g_wn[k] = 0.5f * s;
}

// ---------------------------------------------------------------------------
// Stage 1: fp16-split warp-MMA GEMM + fused per-row top-2 argmax
// Logical k' in [0,768): seg0 = xh*wh, seg1 = xh*wl, seg2 = xl*wh
// ---------------------------------------------------------------------------
__global__ void __launch_bounds__(256) stage1_kernel() {
    extern __shared__ char smem[];
    const uint32_t sbase = smem_to_u32(smem);
    float* wnsS = (float*)(smem + SM_WNS);
    float* mv1 = (float*)(smem + SM_MV1);
    float* mv2 = (float*)(smem + SM_MV2);
    int*   mi  = (int*)(smem + SM_MI);

    const int tid = threadIdx.x;
    const int lane = tid & 31;
    const int wid = tid >> 5;
    const int warp_m = wid & 3;        // 4 warps in M: 32 rows each
    const int warp_n = wid >> 2;       // 2 warps in N: 64 cols each
    const int row0 = blockIdx.x * BM;

    // ldmatrix per-lane base offsets (80B row pitch)
    const uint32_t aBase = sbase + SM_A +
        (uint32_t)((warp_m * 32 + (lane & 15)) * 80 + (lane >> 4) * 16);
    const uint32_t bBase = sbase + SM_B +
        (uint32_t)((warp_n * 64 + (lane & 7) + ((lane >> 4) & 1) * 8) * 80 +
                   ((lane >> 3) & 1) * 16);

    // cp.async assignments: thread covers row (tid>>1), chunks c=(tid&1)*2, +1
    const int ldRow = tid >> 1;
    const int ldC0 = (tid & 1) * 2;

    // persistent per-thread argmax state: 4 rows (i in {0,1}, h in {0,1})
    float best1[4], best2[4];
    int idx1[4];
    #pragma unroll
    for (int r = 0; r < 4; r++) { best1[r] = -3.4e38f; best2[r] = -3.4e38f; idx1[r] = 0; }

    for (int ch = 0; ch < NCHUNK; ch++) {
        const int kc = ch * BN;

        if (tid < BN) wnsS[tid] = g_wn[kc + tid];

        float acc[2][8][4];
        #pragma unroll
        for (int i = 0; i < 2; i++)
            #pragma unroll
            for (int j = 0; j < 8; j++)
                #pragma unroll
                for (int q = 0; q < 4; q++) acc[i][j][q] = 0.0f;

        // prologue: load k-iter 0 into buf 0
        {
            const __half* As = g_xh;
            const __half* Bs = g_wh;
            #pragma unroll
            for (int q = 0; q < 2; q++) {
                int c = ldC0 + q;
                cpasync16(sbase + SM_A + (uint32_t)(ldRow * 80 + c * 16),
                          As + (size_t)(row0 + ldRow) * Dd + c * 8);
                cpasync16(sbase + SM_B + (uint32_t)(ldRow * 80 + c * 16),
                          Bs + (size_t)(kc + ldRow) * Dd + c * 8);
            }
            CP_COMMIT();
        }

        for (int kt = 0; kt < NK; kt++) {
            const int buf = kt & 1;
            if (kt + 1 < NK) {
                const int nt = kt + 1;
                const __half* As = (nt < 16) ? g_xh : g_xl;
                const __half* Bs = (nt >= 8 && nt < 16) ? g_wl : g_wh;
                const int kk = (nt & 7) * 32;
                const uint32_t db = (uint32_t)((buf ^ 1) * TBUF);
                #pragma unroll
                for (int q = 0; q < 2; q++) {
                    int c = ldC0 + q;
                    cpasync16(sbase + SM_A + db + (uint32_t)(ldRow * 80 + c * 16),
                              As + (size_t)(row0 + ldRow) * Dd + kk + c * 8);
                    cpasync16(sbase + SM_B + db + (uint32_t)(ldRow * 80 + c * 16),
                              Bs + (size_t)(kc + ldRow) * Dd + kk + c * 8);
                }
                CP_COMMIT();
                CP_WAIT1();
            } else {
                CP_WAIT0();
            }
            __syncthreads();

            const uint32_t bo = (uint32_t)(buf * TBUF);
            #pragma unroll
            for (int ks = 0; ks < 2; ks++) {
                uint32_t a[2][4];
                #pragma unroll
                for (int i = 0; i < 2; i++)
                    LDSM_X4(a[i][0], a[i][1], a[i][2], a[i][3],
                            aBase + bo + (uint32_t)(i * 1280 + ks * 32));
                uint32_t b[8][2];
                #pragma unroll
                for (int jp = 0; jp < 4; jp++)
                    LDSM_X4(b[2 * jp][0], b[2 * jp][1], b[2 * jp + 1][0], b[2 * jp + 1][1],
                            bBase + bo + (uint32_t)(jp * 1280 + ks * 32));
                #pragma unroll
                for (int i = 0; i < 2; i++)
                    #pragma unroll
                    for (int j = 0; j < 8; j++)
                        MMA16816(acc[i][j], a[i], b[j]);
            }
            __syncthreads();
        }

        // fused epilogue: score = acc - 0.5||w||^2 ; per-row top-2
        #pragma unroll
        for (int i = 0; i < 2; i++) {
            #pragma unroll
            for (int h = 0; h < 2; h++) {
                const int r = i * 2 + h;
                #pragma unroll
                for (int j = 0; j < 8; j++) {
                    int col = warp_n * 64 + j * 8 + (lane & 3) * 2;
                    #pragma unroll
                    for (int q = 0; q < 2; q++) {
                        float s = acc[i][j][h * 2 + q] - wnsS[col + q];
                        int k = kc + col + q;
                        if (s > best1[r]) { best2[r] = best1[r]; best1[r] = s; idx1[r] = k; }
                        else if (s > best2[r]) { best2[r] = s; }
                    }
                }
            }
        }
        __syncthreads();   // protect wnsS before next chunk overwrites
    }

    // cross-thread merge: 8 entries per row (warp_n x lane&3)
    const int e = warp_n * 4 + (lane & 3);
    #pragma unroll
    for (int r = 0; r < 4; r++) {
        int row = warp_m * 32 + (r >> 1) * 16 + (lane >> 2) + (r & 1) * 8;
        mv1[row * 8 + e] = best1[r];
        mv2[row * 8 + e] = best2[r];
        mi[row * 8 + e] = idx1[r];
    }
    __syncthreads();

    if (tid < BM) {
        float b1 = -3.4e38f, b2 = -3.4e38f;
        int bi = 0;
        #pragma unroll
        for (int t = 0; t < 8; t++) {
            float v = mv1[tid * 8 + t];
            int ii = mi[tid * 8 + t];
            if (v > b1 || (v == b1 && ii < bi)) { b2 = (b2 > b1) ? b2 : b1; b1 = v; bi = ii; }
            else if (v > b2) b2 = v;
            float v2 = mv2[tid * 8 + t];
            if (v2 > b2) b2 = v2;
        }
        int n = row0 + tid;
        g_idx[n] = bi;
        if (b1 - b2 < MARGIN) {
            unsigned slot = atomicAdd(&g_nflag, 1u);
            if (slot < CAP) {
                g_res[n] = 0ull;
                __threadfence();
                g_flag[slot] = n;
            }
        }
    }
}

// ---------------------------------------------------------------------------
// Rescue: exact fp32 rescore for flagged rows
// ---------------------------------------------------------------------------
__global__ void __launch_bounds__(256) rescue_kernel(const float* __restrict__ X,
                                                    const float* __restrict__ W) {
    unsigned cnt = g_nflag; if (cnt > CAP) cnt = CAP;
    unsigned slot = blockIdx.x >> 1;
    if (slot >= cnt) return;
    int n = (int)g_flag[slot];
    int k0 = (blockIdx.x & 1) * (Kk / 2);

    __shared__ float xs[Dd];
    xs[threadIdx.x] = X[(size_t)n * Dd + threadIdx.x];
    __syncthreads();

    int wid = threadIdx.x >> 5, lane = threadIdx.x & 31;
    float best = -3.4e38f;
    int bidx = 0;
    for (int k = k0 + wid; k < k0 + Kk / 2; k += 8) {
        const float4* wr = (const float4*)(W + (size_t)k * Dd);
        float dot = 0.0f;
        #pragma unroll
        for (int u = 0; u < 2; u++) {
            float4 wv = wr[lane * 2 + u];
            int d = lane * 8 + u * 4;
            dot += wv.x * xs[d] + wv.y * xs[d + 1] + wv.z * xs[d + 2] + wv.w * xs[d + 3];
        }
        #pragma unroll
        for (int o = 16; o > 0; o >>= 1) dot += __shfl_xor_sync(0xffffffffu, dot, o);
        float s = dot - g_wn[k];
        if (s > best) { best = s; bidx = k; }
    }
    if (lane == 0) {
        unsigned u = __float_as_uint(best);
        u = (u & 0x80000000u) ? ~u : (u | 0x80000000u);
        unsigned long long key =
            ((unsigned long long)u << 32) | (unsigned long long)(0xFFFFFFFFu - (unsigned)bidx);
        atomicMax(&g_res[n], key);
    }
}

__global__ void apply_kernel() {
    unsigned cnt = g_nflag; if (cnt > CAP) cnt = CAP;
    unsigned t = blockIdx.x * 256 + threadIdx.x;
    if (t < cnt) {
        int n = (int)g_flag[t];
        unsigned long long key = g_res[n];
        g_idx[n] = (int)(0xFFFFFFFFu - (unsigned)(key & 0xFFFFFFFFull));
    }
}

// ---------------------------------------------------------------------------
__global__ void gather_kernel(const float* __restrict__ W,
                              float* __restrict__ outq,
                              float* __restrict__ outi,
                              int write_idx) {
    int n = blockIdx.x;
    int idx = g_idx[n];
    const float4* src = (const float4*)(W + (size_t)idx * Dd);
    float4* dst = (float4*)(outq + (size_t)n * Dd);
    dst[threadIdx.x] = src[threadIdx.x];
    if (threadIdx.x == 0 && write_idx) outi[n] = (float)idx;
}

// ---------------------------------------------------------------------------
extern "C" void kernel_launch(void* const* d_in, const int* in_sizes, int n_in,
                              void* d_out, int out_size) {
    const float* X = (const float*)d_in[0];
    const float* W = (const float*)d_in[1];
    float* out = (float*)d_out;

    cudaFuncSetAttribute(stage1_kernel,
                         cudaFuncAttributeMaxDynamicSharedMemorySize, SMEM_TOTAL);

    convx_kernel<<<(Nn * Dd / 2 + 255) / 256, 256>>>(X);
    convw_kernel<<<(Kk * Dd / 2 + 255) / 256, 256>>>(W);
    wnorm_kernel<<<Kk / 8, 256>>>(W);

    stage1_kernel<<<Nn / BM, 256, SMEM_TOTAL>>>();

    rescue_kernel<<<2 * CAP, 256>>>(X, W);
    apply_kernel<<<(CAP + 255) / 256, 256>>>();

    int write_idx = (out_size >= Nn * Dd + Nn) ? 1 : 0;
    gather_kernel<<<Nn, 64>>>(W, out, out + (size_t)Nn * Dd, write_idx);
}

// round 5
// speedup vs baseline: 2.5752x; 1.4491x over previous
#include <cuda_runtime.h>
#include <cuda_fp16.h>
#include <cstdint>

#define Nn 32768
#define Dd 256
#define Kk 8192

#define BM 128
#define BN 128
#define BK 64
#define NCHUNK (Kk / BN)        // 64
#define NIT (NCHUNK * 4)        // 256 k-iterations total (4 per chunk)
#define CAP 4096u
#define MARGIN 0.1f

// ---------------------------------------------------------------------------
// Device scratch
// ---------------------------------------------------------------------------
__device__ __half g_xh[Nn * Dd];
__device__ __half g_wh[Kk * Dd];
__device__ float g_wn[Kk];
__device__ int g_idx[Nn];
__device__ unsigned int g_flag[CAP];
__device__ unsigned int g_nflag;
__device__ unsigned long long g_res[Nn];

// ---------------------------------------------------------------------------
__device__ __forceinline__ uint32_t smem_to_u32(const void* p) {
    uint32_t a;
    asm("{ .reg .u64 t; cvta.to.shared.u64 t, %1; cvt.u32.u64 %0, t; }"
        : "=r"(a) : "l"(p));
    return a;
}

__device__ __forceinline__ void cpasync16(uint32_t dst, const void* src) {
    asm volatile("cp.async.cg.shared.global [%0], [%1], 16;" :: "r"(dst), "l"(src));
}

#define CP_COMMIT() asm volatile("cp.async.commit_group;" ::: "memory")
#define CP_WAIT0()  asm volatile("cp.async.wait_group 0;" ::: "memory")

#define LDSM_X4(r0, r1, r2, r3, addr) \
    asm volatile("ldmatrix.sync.aligned.m8n8.x4.shared.b16 {%0,%1,%2,%3}, [%4];" \
        : "=r"(r0), "=r"(r1), "=r"(r2), "=r"(r3) : "r"(addr))

#define MMA16816(c, a, b) \
    asm volatile("mma.sync.aligned.m16n8k16.row.col.f32.f16.f16.f32 " \
        "{%0,%1,%2,%3}, {%4,%5,%6,%7}, {%8,%9}, {%0,%1,%2,%3};" \
        : "+f"((c)[0]), "+f"((c)[1]), "+f"((c)[2]), "+f"((c)[3]) \
        : "r"((a)[0]), "r"((a)[1]), "r"((a)[2]), "r"((a)[3]), \
          "r"((b)[0]), "r"((b)[1]))

// SMEM layout (dynamic), 144B row pitch (odd multiple of 16B -> conflict-free):
//  A (resident): 4 sub-tiles (kt) x 128 rows x 144B = 73728
//  B: 2 bufs x 128 x 144 = 36864
//  wns[2][128] floats = 1024 ; merge arrays 3 x 4096
#define SM_A   0
#define SM_B   73728
#define SM_WNS 110592
#define SM_MV1 111616
#define SM_MV2 115712
#define SM_MI  119808
#define SMEM_TOTAL 123904
#define TSUB 18432   // one 128x64 tile footprint (128 * 144)

// ---------------------------------------------------------------------------
// Preprocessing: fp32 -> fp16 (hi only)
// ---------------------------------------------------------------------------
__global__ void convx_kernel(const float* __restrict__ X) {
    int i = blockIdx.x * 256 + threadIdx.x;
    if (i == 0) g_nflag = 0;
    if (i < Nn * Dd / 2) {
        float2 v = ((const float2*)X)[i];
        ((__half2*)g_xh)[i] = __halves2half2(__float2half(v.x), __float2half(v.y));
    }
}

__global__ void convw_kernel(const float* __restrict__ W) {
    int i = blockIdx.x * 256 + threadIdx.x;
    if (i < Kk * Dd / 2) {
        float2 v = ((const float2*)W)[i];
        ((__half2*)g_wh)[i] = __halves2half2(__float2half(v.x), __float2half(v.y));
    }
}

__global__ void wnorm_kernel(const float* __restrict__ W) {
    int k = blockIdx.x * 8 + (threadIdx.x >> 5);
    int lane = threadIdx.x & 31;
    const float4* wp = (const float4*)(W + (size_t)k * Dd);
    float4 a = wp[lane * 2];
    float4 b = wp[lane * 2 + 1];
    float s = a.x * a.x + a.y * a.y + a.z * a.z + a.w * a.w
            + b.x * b.x + b.y * b.y + b.z * b.z + b.w * b.w;
    #pragma unroll
    for (int o = 16; o > 0; o >>= 1) s += __shfl_xor_sync(0xffffffffu, s, o);
    if (lane == 0) g_wn[k] = 0.5f * s;
}

// ---------------------------------------------------------------------------
// Stage 1: fp16 warp-MMA GEMM (A resident in smem) + fused top-2 argmax
// ---------------------------------------------------------------------------
__global__ void __launch_bounds__(256) stage1_kernel() {
    extern __shared__ char smem[];
    const uint32_t sbase = smem_to_u32(smem);
    float* wnsS = (float*)(smem + SM_WNS);
    float* mv1 = (float*)(smem + SM_MV1);
    float* mv2 = (float*)(smem + SM_MV2);
    int*   mi  = (int*)(smem + SM_MI);

    const int tid = threadIdx.x;
    const int lane = tid & 31;
    const int wid = tid >> 5;
    const int warp_m = wid & 3;        // 4 warps x 32 rows
    const int warp_n = wid >> 2;       // 2 warps x 64 cols
    const int row0 = blockIdx.x * BM;

    const uint32_t aBase = sbase + SM_A +
        (uint32_t)((warp_m * 32 + (lane & 15)) * 144 + (lane >> 4) * 16);
    const uint32_t bBase = sbase + SM_B +
        (uint32_t)((warp_n * 64 + (lane & 7) + ((lane >> 4) & 1) * 8) * 144 +
                   ((lane >> 3) & 1) * 16);

    const int ldRow = tid >> 1;

    // ---- prologue: resident A (whole 128x256 X tile) + B(it=0) + wns(ch=0) ----
    {
        const int c0 = (tid & 1) * 16;
        #pragma unroll
        for (int q = 0; q < 16; q++) {
            int c = c0 + q;                       // 16B chunk index, 0..31
            cpasync16(sbase + SM_A + (uint32_t)((c >> 3) * TSUB + ldRow * 144 + (c & 7) * 16),
                      g_xh + (size_t)(row0 + ldRow) * Dd + c * 8);
        }
        const int bc0 = (tid & 1) * 4;
        #pragma unroll
        for (int q = 0; q < 4; q++) {
            int c = bc0 + q;
            cpasync16(sbase + SM_B + (uint32_t)(ldRow * 144 + c * 16),
                      g_wh + (size_t)ldRow * Dd + c * 8);
        }
        CP_COMMIT();
        if (tid < BN) wnsS[tid] = g_wn[tid];
    }

    float best1[4], best2[4];
    int idx1[4];
    #pragma unroll
    for (int r = 0; r < 4; r++) { best1[r] = -3.4e38f; best2[r] = -3.4e38f; idx1[r] = 0; }

    float acc[2][8][4];

    for (int it = 0; it < NIT; it++) {
        const int ch = it >> 2;
        const int kt = it & 3;
        const int buf = it & 1;

        CP_WAIT0();
        __syncthreads();

        // prefetch next B tile into the other buffer
        if (it + 1 < NIT) {
            const int nch = (it + 1) >> 2;
            const int nkt = (it + 1) & 3;
            const uint32_t db = (uint32_t)((buf ^ 1) * TSUB);
            const int bc0 = (tid & 1) * 4;
            #pragma unroll
            for (int q = 0; q < 4; q++) {
                int c = bc0 + q;
                cpasync16(sbase + SM_B + db + (uint32_t)(ldRow * 144 + c * 16),
                          g_wh + (size_t)(nch * BN + ldRow) * Dd + nkt * BK + c * 8);
            }
            CP_COMMIT();
        }

        if (kt == 0) {
            #pragma unroll
            for (int i = 0; i < 2; i++)
                #pragma unroll
                for (int j = 0; j < 8; j++)
                    #pragma unroll
                    for (int q = 0; q < 4; q++) acc[i][j][q] = 0.0f;
            if (ch + 1 < NCHUNK && tid < BN)
                wnsS[((ch + 1) & 1) * BN + tid] = g_wn[(ch + 1) * BN + tid];
        }

        // compute: 4 k-steps of 16 over this 64-wide slab
        const uint32_t ao = (uint32_t)(kt * TSUB);
        const uint32_t bo = (uint32_t)(buf * TSUB);
        #pragma unroll
        for (int ks = 0; ks < 4; ks++) {
            uint32_t a[2][4];
            #pragma unroll
            for (int i = 0; i < 2; i++)
                LDSM_X4(a[i][0], a[i][1], a[i][2], a[i][3],
                        aBase + ao + (uint32_t)(i * 2304 + ks * 32));
            uint32_t b[8][2];
            #pragma unroll
            for (int jp = 0; jp < 4; jp++)
                LDSM_X4(b[2 * jp][0], b[2 * jp][1], b[2 * jp + 1][0], b[2 * jp + 1][1],
                        bBase + bo + (uint32_t)(jp * 2304 + ks * 32));
            #pragma unroll
            for (int i = 0; i < 2; i++)
                #pragma unroll
                for (int j = 0; j < 8; j++)
                    MMA16816(acc[i][j], a[i], b[j]);
        }

        // fused epilogue at chunk end
        if (kt == 3) {
            const int kc = ch * BN;
            const float* wn = wnsS + (ch & 1) * BN;
            #pragma unroll
            for (int i = 0; i < 2; i++) {
                #pragma unroll
                for (int h = 0; h < 2; h++) {
                    const int r = i * 2 + h;
                    #pragma unroll
                    for (int j = 0; j < 8; j++) {
                        int col = warp_n * 64 + j * 8 + (lane & 3) * 2;
                        #pragma unroll
                        for (int q = 0; q < 2; q++) {
                            float s = acc[i][j][h * 2 + q] - wn[col + q];
                            int k = kc + col + q;
                            if (s > best1[r]) { best2[r] = best1[r]; best1[r] = s; idx1[r] = k; }
                            else if (s > best2[r]) { best2[r] = s; }
                        }
                    }
                }
            }
        }
    }

    // cross-thread merge: 8 entries per row
    const int e = warp_n * 4 + (lane & 3);
    #pragma unroll
    for (int r = 0; r < 4; r++) {
        int row = warp_m * 32 + (r >> 1) * 16 + (lane >> 2) + (r & 1) * 8;
        mv1[row * 8 + e] = best1[r];
        mv2[row * 8 + e] = best2[r];
        mi[row * 8 + e] = idx1[r];
    }
    __syncthreads();

    if (tid < BM) {
        float b1 = -3.4e38f, b2 = -3.4e38f;
        int bi = 0;
        #pragma unroll
        for (int t = 0; t < 8; t++) {
            float v = mv1[tid * 8 + t];
            int ii = mi[tid * 8 + t];
            if (v > b1 || (v == b1 && ii < bi)) { b2 = (b2 > b1) ? b2 : b1; b1 = v; bi = ii; }
            else if (v > b2) b2 = v;
            float v2 = mv2[tid * 8 + t];
            if (v2 > b2) b2 = v2;
        }
        int n = row0 + tid;
        g_idx[n] = bi;
        if (b1 - b2 < MARGIN) {
            unsigned slot = atomicAdd(&g_nflag, 1u);
            if (slot < CAP) {
                g_res[n] = 0ull;
                __threadfence();
                g_flag[slot] = n;
            }
        }
    }
}

// ---------------------------------------------------------------------------
// Rescue: exact fp32 rescore for flagged rows (block = (row, k-half))
// ---------------------------------------------------------------------------
__global__ void __launch_bounds__(256) rescue_kernel(const float* __restrict__ X,
                                                    const float* __restrict__ W) {
    unsigned cnt = g_nflag; if (cnt > CAP) cnt = CAP;
    unsigned slot = blockIdx.x >> 1;
    if (slot >= cnt) return;
    int n = (int)g_flag[slot];
    int k0 = (blockIdx.x & 1) * (Kk / 2);

    __shared__ float xs[Dd];
    xs[threadIdx.x] = X[(size_t)n * Dd + threadIdx.x];
    __syncthreads();

    int wid = threadIdx.x >> 5, lane = threadIdx.x & 31;
    float best = -3.4e38f;
    int bidx = 0;
    for (int k = k0 + wid; k < k0 + Kk / 2; k += 8) {
        const float4* wr = (const float4*)(W + (size_t)k * Dd);
        float dot = 0.0f;
        #pragma unroll
        for (int u = 0; u < 2; u++) {
            float4 wv = wr[lane * 2 + u];
            int d = lane * 8 + u * 4;
            dot += wv.x * xs[d] + wv.y * xs[d + 1] + wv.z * xs[d + 2] + wv.w * xs[d + 3];
        }
        #pragma unroll
        for (int o = 16; o > 0; o >>= 1) dot += __shfl_xor_sync(0xffffffffu, dot, o);
        float s = dot - g_wn[k];
        if (s > best) { best = s; bidx = k; }
    }
    if (lane == 0) {
        unsigned u = __float_as_uint(best);
        u = (u & 0x80000000u) ? ~u : (u | 0x80000000u);
        unsigned long long key =
            ((unsigned long long)u << 32) | (unsigned long long)(0xFFFFFFFFu - (unsigned)bidx);
        atomicMax(&g_res[n], key);
    }
}

__global__ void apply_kernel() {
    unsigned cnt = g_nflag; if (cnt > CAP) cnt = CAP;
    unsigned t = blockIdx.x * 256 + threadIdx.x;
    if (t < cnt) {
        int n = (int)g_flag[t];
        unsigned long long key = g_res[n];
        g_idx[n] = (int)(0xFFFFFFFFu - (unsigned)(key & 0xFFFFFFFFull));
    }
}

// ---------------------------------------------------------------------------
__global__ void gather_kernel(const float* __restrict__ W,
                              float* __restrict__ outq,
                              float* __restrict__ outi,
                              int write_idx) {
    int n = blockIdx.x;
    int idx = g_idx[n];
    const float4* src = (const float4*)(W + (size_t)idx * Dd);
    float4* dst = (float4*)(outq + (size_t)n * Dd);
    dst[threadIdx.x] = src[threadIdx.x];
    if (threadIdx.x == 0 && write_idx) outi[n] = (float)idx;
}

// ---------------------------------------------------------------------------
extern "C" void kernel_launch(void* const* d_in, const int* in_sizes, int n_in,
                              void* d_out, int out_size) {
    const float* X = (const float*)d_in[0];
    const float* W = (const float*)d_in[1];
    float* out = (float*)d_out;

    cudaFuncSetAttribute(stage1_kernel,
                         cudaFuncAttributeMaxDynamicSharedMemorySize, SMEM_TOTAL);

    convx_kernel<<<(Nn * Dd / 2 + 255) / 256, 256>>>(X);
    convw_kernel<<<(Kk * Dd / 2 + 255) / 256, 256>>>(W);
    wnorm_kernel<<<Kk / 8, 256>>>(W);

    stage1_kernel<<<Nn / BM, 256, SMEM_TOTAL>>>();

    rescue_kernel<<<2 * CAP, 256>>>(X, W);
    apply_kernel<<<(CAP + 255) / 256, 256>>>();

    int write_idx = (out_size >= Nn * Dd + Nn) ? 1 : 0;
    gather_kernel<<<Nn, 64>>>(W, out, out + (size_t)Nn * Dd, write_idx);
}

// round 7
// speedup vs baseline: 3.3976x; 1.3193x over previous
#include <cuda_runtime.h>
#include <cuda_fp16.h>
#include <cstdint>

#define Nn 32768
#define Dd 256
#define Kk 8192

#define BM 128
#define BN 128
#define BK 32
#define NCHUNK (Kk / BN)        // 64
#define NIT (NCHUNK * 8)        // 512 iterations (8 x 32-dim slabs per chunk)
#define CAP 8192u
#define MARGIN 0.1f
#define KSPLIT 8

// ---------------------------------------------------------------------------
// Device scratch
// ---------------------------------------------------------------------------
__device__ __half g_xh[Nn * Dd];
__device__ __half g_wh[Kk * Dd];
__device__ float g_wn[Kk];
__device__ int g_idx[Nn];
__device__ unsigned int g_flag[CAP];
__device__ unsigned int g_nflag;
__device__ unsigned long long g_res[Nn];

// ---------------------------------------------------------------------------
__device__ __forceinline__ uint32_t smem_to_u32(const void* p) {
    uint32_t a;
    asm("{ .reg .u64 t; cvta.to.shared.u64 t, %1; cvt.u32.u64 %0, t; }"
        : "=r"(a) : "l"(p));
    return a;
}

__device__ __forceinline__ void cpasync16(uint32_t dst, const void* src) {
    asm volatile("cp.async.cg.shared.global [%0], [%1], 16;" :: "r"(dst), "l"(src));
}

#define CP_COMMIT() asm volatile("cp.async.commit_group;" ::: "memory")
#define CP_WAIT2()  asm volatile("cp.async.wait_group 2;" ::: "memory")

#define LDSM_X4(r0, r1, r2, r3, addr) \
    asm volatile("ldmatrix.sync.aligned.m8n8.x4.shared.b16 {%0,%1,%2,%3}, [%4];" \
        : "=r"(r0), "=r"(r1), "=r"(r2), "=r"(r3) : "r"(addr))

#define MMA16816(c, a, b) \
    asm volatile("mma.sync.aligned.m16n8k16.row.col.f32.f16.f16.f32 " \
        "{%0,%1,%2,%3}, {%4,%5,%6,%7}, {%8,%9}, {%0,%1,%2,%3};" \
        : "+f"((c)[0]), "+f"((c)[1]), "+f"((c)[2]), "+f"((c)[3]) \
        : "r"((a)[0]), "r"((a)[1]), "r"((a)[2]), "r"((a)[3]), \
          "r"((b)[0]), "r"((b)[1]))

// SMEM layout (stage1, dynamic), 80B row pitch (odd multiple of 16B):
//  4 pipeline stages x (A 128x80 + B 128x80) = 4 x 20480 = 81920
//  wns[2][128] = 1024 ; merge mv1/mv2/mi = 3 x 4096
#define SM_STAGE  20480
#define SM_WNS    81920
#define SM_MV1    82944
#define SM_MV2    87040
#define SM_MI     91136
#define SMEM_TOTAL 95232
#define ATILE 0
#define BTILE 10240

// ---------------------------------------------------------------------------
// Preprocessing: fp32 -> fp16
// ---------------------------------------------------------------------------
__global__ void convx_kernel(const float* __restrict__ X) {
    int i = blockIdx.x * 256 + threadIdx.x;
    if (i == 0) g_nflag = 0;
    if (i < Nn * Dd / 2) {
        float2 v = ((const float2*)X)[i];
        ((__half2*)g_xh)[i] = __halves2half2(__float2half(v.x), __float2half(v.y));
    }
}

__global__ void convw_kernel(const float* __restrict__ W) {
    int i = blockIdx.x * 256 + threadIdx.x;
    if (i < Kk * Dd / 2) {
        float2 v = ((const float2*)W)[i];
        ((__half2*)g_wh)[i] = __halves2half2(__float2half(v.x), __float2half(v.y));
    }
}

__global__ void wnorm_kernel(const float* __restrict__ W) {
    int k = blockIdx.x * 8 + (threadIdx.x >> 5);
    int lane = threadIdx.x & 31;
    const float4* wp = (const float4*)(W + (size_t)k * Dd);
    float4 a = wp[lane * 2];
    float4 b = wp[lane * 2 + 1];
    float s = a.x * a.x + a.y * a.y + a.z * a.z + a.w * a.w
            + b.x * b.x + b.y * b.y + b.z * b.z + b.w * b.w;
    #pragma unroll
    for (int o = 16; o > 0; o >>= 1) s += __shfl_xor_sync(0xffffffffu, s, o);
    if (lane == 0) g_wn[k] = 0.5f * s;
}

// ---------------------------------------------------------------------------
// Stage 1: fp16 warp-MMA GEMM, 4-stage cp.async pipeline, 2 CTAs/SM
// ---------------------------------------------------------------------------
__global__ void __launch_bounds__(256, 2) stage1_kernel() {
    extern __shared__ char smem[];
    const uint32_t sbase = smem_to_u32(smem);
    float* wnsS = (float*)(smem + SM_WNS);
    float* mv1 = (float*)(smem + SM_MV1);
    float* mv2 = (float*)(smem + SM_MV2);
    int*   mi  = (int*)(smem + SM_MI);

    const int tid = threadIdx.x;
    const int lane = tid & 31;
    const int wid = tid >> 5;
    const int warp_m = wid & 3;        // 4 warps x 32 rows
    const int warp_n = wid >> 2;       // 2 warps x 64 cols
    const int row0 = blockIdx.x * BM;

    const uint32_t aBase = sbase + ATILE +
        (uint32_t)((warp_m * 32 + (lane & 15)) * 80 + (lane >> 4) * 16);
    const uint32_t bBase = sbase + BTILE +
        (uint32_t)((warp_n * 64 + (lane & 7) + ((lane >> 4) & 1) * 8) * 80 +
                   ((lane >> 3) & 1) * 16);

    // per-iter loads: A 8KB + B 8KB; thread covers row tid>>1, chunks (tid&1)*2+q
    const int ldRow = tid >> 1;
    const int ldC0 = (tid & 1) * 2;

    // prologue: fill 3 stages (iters 0,1,2 = ch0, kt 0..2) + wns(ch0)
    #pragma unroll
    for (int p = 0; p < 3; p++) {
        const uint32_t st = sbase + (uint32_t)(p * SM_STAGE);
        #pragma unroll
        for (int q = 0; q < 2; q++) {
            int c = ldC0 + q;
            cpasync16(st + ATILE + (uint32_t)(ldRow * 80 + c * 16),
                      g_xh + (size_t)(row0 + ldRow) * Dd + p * BK + c * 8);
            cpasync16(st + BTILE + (uint32_t)(ldRow * 80 + c * 16),
                      g_wh + (size_t)ldRow * Dd + p * BK + c * 8);
        }
        CP_COMMIT();
    }
    if (tid < BN) wnsS[tid] = g_wn[tid];

    float best1[4], best2[4];
    int idx1[4];
    #pragma unroll
    for (int r = 0; r < 4; r++) { best1[r] = -3.4e38f; best2[r] = -3.4e38f; idx1[r] = 0; }

    float acc[2][8][4];

    for (int it = 0; it < NIT; it++) {
        const int ch = it >> 3;
        const int kt = it & 7;

        CP_WAIT2();
        __syncthreads();

        // prefetch stage it+3 (wrap for the tail: dummy loads keep group count uniform)
        {
            const int nit = (it + 3) & (NIT - 1);
            const int nch = nit >> 3;
            const int nkt = nit & 7;
            const uint32_t st = sbase + (uint32_t)(((it + 3) & 3) * SM_STAGE);
            #pragma unroll
            for (int q = 0; q < 2; q++) {
                int c = ldC0 + q;
                cpasync16(st + ATILE + (uint32_t)(ldRow * 80 + c * 16),
                          g_xh + (size_t)(row0 + ldRow) * Dd + nkt * BK + c * 8);
                cpasync16(st + BTILE + (uint32_t)(ldRow * 80 + c * 16),
                          g_wh + (size_t)(nch * BN + ldRow) * Dd + nkt * BK + c * 8);
            }
            CP_COMMIT();
        }

        if (kt == 0) {
            #pragma unroll
            for (int i = 0; i < 2; i++)
                #pragma unroll
                for (int j = 0; j < 8; j++)
                    #pragma unroll
                    for (int q = 0; q < 4; q++) acc[i][j][q] = 0.0f;
            if (ch + 1 < NCHUNK && tid < BN)
                wnsS[((ch + 1) & 1) * BN + tid] = g_wn[(ch + 1) * BN + tid];
        }

        // compute: 2 k16-steps on this 32-dim slab
        const uint32_t so = (uint32_t)((it & 3) * SM_STAGE);
        #pragma unroll
        for (int ks = 0; ks < 2; ks++) {
            uint32_t a[2][4];
            #pragma unroll
            for (int i = 0; i < 2; i++)
                LDSM_X4(a[i][0], a[i][1], a[i][2], a[i][3],
                        aBase + so + (uint32_t)(i * 1280 + ks * 32));
            uint32_t b[8][2];
            #pragma unroll
            for (int jp = 0; jp < 4; jp++)
                LDSM_X4(b[2 * jp][0], b[2 * jp][1], b[2 * jp + 1][0], b[2 * jp + 1][1],
                        bBase + so + (uint32_t)(jp * 1280 + ks * 32));
            #pragma unroll
            for (int i = 0; i < 2; i++)
                #pragma unroll
                for (int j = 0; j < 8; j++)
                    MMA16816(acc[i][j], a[i], b[j]);
        }

        // fused top-2 argmax at chunk end
        if (kt == 7) {
            const int kc = ch * BN;
            const float* wn = wnsS + (ch & 1) * BN;
            #pragma unroll
            for (int i = 0; i < 2; i++) {
                #pragma unroll
                for (int h = 0; h < 2; h++) {
                    const int r = i * 2 + h;
                    #pragma unroll
                    for (int j = 0; j < 8; j++) {
                        int col = warp_n * 64 + j * 8 + (lane & 3) * 2;
                        #pragma unroll
                        for (int q = 0; q < 2; q++) {
                            float s = acc[i][j][h * 2 + q] - wn[col + q];
                            int k = kc + col + q;
                            if (s > best1[r]) { best2[r] = best1[r]; best1[r] = s; idx1[r] = k; }
                            else if (s > best2[r]) { best2[r] = s; }
                        }
                    }
                }
            }
        }
    }

    // cross-thread merge: 8 entries per row
    const int e = warp_n * 4 + (lane & 3);
    #pragma unroll
    for (int r = 0; r < 4; r++) {
        int row = warp_m * 32 + (r >> 1) * 16 + (lane >> 2) + (r & 1) * 8;
        mv1[row * 8 + e] = best1[r];
        mv2[row * 8 + e] = best2[r];
        mi[row * 8 + e] = idx1[r];
    }
    __syncthreads();

    if (tid < BM) {
        float b1 = -3.4e38f, b2 = -3.4e38f;
        int bi = 0;
        #pragma unroll
        for (int t = 0; t < 8; t++) {
            float v = mv1[tid * 8 + t];
            int ii = mi[tid * 8 + t];
            if (v > b1 || (v == b1 && ii < bi)) { b2 = (b2 > b1) ? b2 : b1; b1 = v; bi = ii; }
            else if (v > b2) b2 = v;
            float v2 = mv2[tid * 8 + t];
            if (v2 > b2) b2 = v2;
        }
        int n = row0 + tid;
        g_idx[n] = bi;
        if (b1 - b2 < MARGIN) {
            unsigned slot = atomicAdd(&g_nflag, 1u);
            if (slot < CAP) {
                g_res[n] = 0ull;
                __threadfence();
                g_flag[slot] = n;
            }
        }
    }
}

// ---------------------------------------------------------------------------
// Batched rescue: 32 flagged rows per block x 1024-codeword K-split.
// Exact fp32 rescore; combine via packed atomicMax.
// Uses DYNAMIC smem (66048 B > 48KB static limit): xs[32][256] then ws[32*260].
// ---------------------------------------------------------------------------
#define WPITCH 260   // floats per padded W row in smem
#define RS_XS 0
#define RS_WS (32 * 256 * 4)
#define RS_SMEM (RS_WS + 32 * WPITCH * 4)   // 66048 bytes

__global__ void __launch_bounds__(256) rescue_kernel(const float* __restrict__ X,
                                                    const float* __restrict__ W) {
    extern __shared__ char rsm[];
    float* xs = (float*)(rsm + RS_XS);          // [32][256]
    float* ws = (float*)(rsm + RS_WS);          // [32 * WPITCH]

    unsigned cnt = g_nflag; if (cnt > CAP) cnt = CAP;
    const unsigned grp = blockIdx.x >> 3;          // row group (32 rows)
    const int ksp = blockIdx.x & 7;                // k range [ksp*1024, +1024)
    if (grp * 32 >= cnt) return;

    const int tid = threadIdx.x;
    const int ty = tid >> 5;                       // warp id: owns rows ty*4..ty*4+3
    const int tx = tid & 31;

    // load 32 X rows (row = tid>>3, 8 float4 per thread)
    {
        const int r = tid >> 3, seg = tid & 7;
        unsigned slot = grp * 32 + r;
        int n = (int)g_flag[slot < cnt ? slot : (grp * 32)];
        const float4* src = (const float4*)(X + (size_t)n * Dd);
        #pragma unroll
        for (int q = 0; q < 8; q++)
            *(float4*)&xs[r * 256 + (seg * 8 + q) * 4] = src[seg * 8 + q];
    }

    unsigned long long key[4];
    #pragma unroll
    for (int i = 0; i < 4; i++) key[i] = 0ull;

    const int k0 = ksp * (Kk / KSPLIT);
    for (int kc = 0; kc < Kk / KSPLIT; kc += 32) {
        __syncthreads();
        // stage 32 codewords
        {
            const int kr = tid >> 3, seg = tid & 7;
            const float4* src = (const float4*)(W + (size_t)(k0 + kc + kr) * Dd);
            #pragma unroll
            for (int q = 0; q < 8; q++)
                *(float4*)&ws[kr * WPITCH + (seg * 8 + q) * 4] = src[seg * 8 + q];
        }
        __syncthreads();

        const int k = k0 + kc + tx;
        float dot[4];
        #pragma unroll
        for (int i = 0; i < 4; i++) dot[i] = 0.0f;
        #pragma unroll
        for (int d = 0; d < 256; d += 4) {
            float4 wv = *(const float4*)&ws[tx * WPITCH + d];
            #pragma unroll
            for (int i = 0; i < 4; i++) {
                float4 xv = *(const float4*)&xs[(ty * 4 + i) * 256 + d];
                dot[i] += wv.x * xv.x + wv.y * xv.y + wv.z * xv.z + wv.w * xv.w;
            }
        }
        const float wn = g_wn[k];
        #pragma unroll
        for (int i = 0; i < 4; i++) {
            float s = dot[i] - wn;
            unsigned u = __float_as_uint(s);
            u = (u & 0x80000000u) ? ~u : (u | 0x80000000u);
            unsigned long long kk2 =
                ((unsigned long long)u << 32) | (unsigned long long)(0xFFFFFFFFu - (unsigned)k);
            if (kk2 > key[i]) key[i] = kk2;
        }
    }

    // warp-reduce max per row, then atomicMax
    #pragma unroll
    for (int i = 0; i < 4; i++) {
        unsigned long long kv = key[i];
        #pragma unroll
        for (int o = 16; o > 0; o >>= 1) {
            unsigned long long other = __shfl_xor_sync(0xffffffffu, kv, o);
            if (other > kv) kv = other;
        }
        if (tx == 0) {
            unsigned slot = grp * 32 + ty * 4 + i;
            if (slot < cnt) atomicMax(&g_res[g_flag[slot]], kv);
        }
    }
}

__global__ void apply_kernel() {
    unsigned cnt = g_nflag; if (cnt > CAP) cnt = CAP;
    unsigned t = blockIdx.x * 256 + threadIdx.x;
    if (t < cnt) {
        int n = (int)g_flag[t];
        unsigned long long key = g_res[n];
        g_idx[n] = (int)(0xFFFFFFFFu - (unsigned)(key & 0xFFFFFFFFull));
    }
}

// ---------------------------------------------------------------------------
__global__ void gather_kernel(const float* __restrict__ W,
                              float* __restrict__ outq,
                              float* __restrict__ outi,
                              int write_idx) {
    int n = blockIdx.x;
    int idx = g_idx[n];
    const float4* src = (const float4*)(W + (size_t)idx * Dd);
    float4* dst = (float4*)(outq + (size_t)n * Dd);
    dst[threadIdx.x] = src[threadIdx.x];
    if (threadIdx.x == 0 && write_idx) outi[n] = (float)idx;
}

// ---------------------------------------------------------------------------
extern "C" void kernel_launch(void* const* d_in, const int* in_sizes, int n_in,
                              void* d_out, int out_size) {
    const float* X = (const float*)d_in[0];
    const float* W = (const float*)d_in[1];
    float* out = (float*)d_out;

    cudaFuncSetAttribute(stage1_kernel,
                         cudaFuncAttributeMaxDynamicSharedMemorySize, SMEM_TOTAL);
    cudaFuncSetAttribute(rescue_kernel,
                         cudaFuncAttributeMaxDynamicSharedMemorySize, RS_SMEM);

    convx_kernel<<<(Nn * Dd / 2 + 255) / 256, 256>>>(X);
    convw_kernel<<<(Kk * Dd / 2 + 255) / 256, 256>>>(W);
    wnorm_kernel<<<Kk / 8, 256>>>(W);

    stage1_kernel<<<Nn / BM, 256, SMEM_TOTAL>>>();

    rescue_kernel<<<(CAP / 32) * KSPLIT, 256, RS_SMEM>>>(X, W);
    apply_kernel<<<(CAP + 255) / 256, 256>>>();

    int write_idx = (out_size >= Nn * Dd + Nn) ? 1 : 0;
    gather_kernel<<<Nn, 64>>>(W, out, out + (size_t)Nn * Dd, write_idx);
}